// round 3
// baseline (speedup 1.0000x reference)
#include <cuda_runtime.h>

#define NN 128
#define LFULL 1024
#define CC 512
#define KTOT 2045
#define L1S 1023
#define L2S 1022

static __device__ __constant__ float INV_T = 14.2857142857142857f; // 1/0.07

// Scratch (device globals — allocation-free rule)
__device__ float g_U[(size_t)NN * L1S * CC];     // 268 MB: U = T @ W, rows (n,l)
__device__ float g_tb[L1S * NN];                 // tb[l][n] = t[n,l+s] . b
__device__ float g_tmp[(size_t)L1S * NN * NN];   // 67 MB: Gram tiles [l][n][m]
__device__ unsigned int g_cnt[2];                // accuracy counters

__global__ void init_kernel() { g_cnt[0] = 0u; g_cnt[1] = 0u; }

// tb[l][n] = dot(timesteps[n, l+step, :], b)
__global__ void tb_kernel(const float* __restrict__ t, const float* __restrict__ b,
                          int Lp, int step) {
    int l = blockIdx.x, n = threadIdx.x;
    const float4* r4 = (const float4*)(t + ((size_t)n * LFULL + l + step) * CC);
    const float4* b4 = (const float4*)b;
    float s = 0.f;
#pragma unroll 8
    for (int i = 0; i < CC / 4; i++) {
        float4 a = r4[i], bb = b4[i];
        s += a.x * bb.x + a.y * bb.y + a.z * bb.z + a.w * bb.w;
    }
    g_tb[l * NN + n] = s;
}

// U[r, p] = sum_c T_row(r)[c] * W[c, p]; r = n*Lp + l, T row = timesteps[n, l+step, :]
// Tiles: 128x128x8, 256 threads, 8x8 per thread.
__global__ __launch_bounds__(256, 2)
void gemmU_kernel(const float* __restrict__ T, const float* __restrict__ W,
                  int Lp, int step) {
    __shared__ float As[8][128];
    __shared__ float Bs[8][128];
    __shared__ unsigned rowbase[128];
    int tid = threadIdx.x;
    int r0 = blockIdx.y * 128;
    if (tid < 128) {
        int r = r0 + tid;
        int n = r / Lp;
        int l = r - n * Lp;
        rowbase[tid] = (unsigned)((n * LFULL + l + step) * CC);
    }
    __syncthreads();
    int colbase = blockIdx.x * 128;
    int arow = tid >> 1, acol = (tid & 1) * 4;
    int brow = tid >> 5, bcol = (tid & 31) * 4;
    int tx = tid & 15, ty = tid >> 4;
    float acc[8][8] = {};
    for (int kt = 0; kt < CC; kt += 8) {
        float4 a = *(const float4*)(T + rowbase[arow] + kt + acol);
        float4 b = *(const float4*)(W + (size_t)(kt + brow) * CC + colbase + bcol);
        __syncthreads();
        As[acol + 0][arow] = a.x; As[acol + 1][arow] = a.y;
        As[acol + 2][arow] = a.z; As[acol + 3][arow] = a.w;
        *(float4*)&Bs[brow][bcol] = b;
        __syncthreads();
#pragma unroll
        for (int kk = 0; kk < 8; kk++) {
            float ar[8], br[8];
            *(float4*)(ar)     = *(const float4*)&As[kk][ty * 8];
            *(float4*)(ar + 4) = *(const float4*)&As[kk][ty * 8 + 4];
            *(float4*)(br)     = *(const float4*)&Bs[kk][tx * 8];
            *(float4*)(br + 4) = *(const float4*)&Bs[kk][tx * 8 + 4];
#pragma unroll
            for (int i = 0; i < 8; i++)
#pragma unroll
                for (int j = 0; j < 8; j++)
                    acc[i][j] = fmaf(ar[i], br[j], acc[i][j]);
        }
    }
#pragma unroll
    for (int i = 0; i < 8; i++) {
        size_t base = (size_t)(r0 + ty * 8 + i) * CC + colbase + tx * 8;
        *(float4*)&g_U[base]     = make_float4(acc[i][0], acc[i][1], acc[i][2], acc[i][3]);
        *(float4*)&g_U[base + 4] = make_float4(acc[i][4], acc[i][5], acc[i][6], acc[i][7]);
    }
}

// Per-l Gram: G[n,m] = sum_k U[n,l,k] * P[m,l,k] (+ tb[n]); also NCE accuracy count.
__global__ __launch_bounds__(256, 2)
void gemmL_kernel(const float* __restrict__ P, int Lp, int stepIdx) {
    int l = blockIdx.x;
    __shared__ float As[8][128];
    __shared__ float Bs[8][128];
    __shared__ float pos[128];
    __shared__ unsigned char flg[128][16];
    int tid = threadIdx.x;
    int row = tid >> 1, koff = (tid & 1) * 4;
    int tx = tid & 15, ty = tid >> 4;
    const float* ubase = g_U + ((size_t)row * Lp + l) * CC + koff;
    const float* pbase = P + ((size_t)row * LFULL + l) * CC + koff;
    float acc[8][8] = {};
    for (int kt = 0; kt < CC; kt += 8) {
        float4 a = *(const float4*)(ubase + kt);
        float4 b = *(const float4*)(pbase + kt);
        __syncthreads();
        As[koff + 0][row] = a.x; As[koff + 1][row] = a.y;
        As[koff + 2][row] = a.z; As[koff + 3][row] = a.w;
        Bs[koff + 0][row] = b.x; Bs[koff + 1][row] = b.y;
        Bs[koff + 2][row] = b.z; Bs[koff + 3][row] = b.w;
        __syncthreads();
#pragma unroll
        for (int kk = 0; kk < 8; kk++) {
            float ar[8], br[8];
            *(float4*)(ar)     = *(const float4*)&As[kk][ty * 8];
            *(float4*)(ar + 4) = *(const float4*)&As[kk][ty * 8 + 4];
            *(float4*)(br)     = *(const float4*)&Bs[kk][tx * 8];
            *(float4*)(br + 4) = *(const float4*)&Bs[kk][tx * 8 + 4];
#pragma unroll
            for (int i = 0; i < 8; i++)
#pragma unroll
                for (int j = 0; j < 8; j++)
                    acc[i][j] = fmaf(ar[i], br[j], acc[i][j]);
        }
    }
    // Epilogue: add tb (row term), capture diagonal, accuracy flags, staged store.
    float tbv[8];
#pragma unroll
    for (int i = 0; i < 8; i++) tbv[i] = g_tb[l * NN + ty * 8 + i];
#pragma unroll
    for (int i = 0; i < 8; i++)
#pragma unroll
        for (int j = 0; j < 8; j++) acc[i][j] += tbv[i];
    if (ty == tx) {
#pragma unroll
        for (int i = 0; i < 8; i++) pos[ty * 8 + i] = acc[i][i];
    }
    __syncthreads();
#pragma unroll
    for (int i = 0; i < 8; i++) {
        int n = ty * 8 + i;
        float pn = pos[n];
        bool ok = true;
#pragma unroll
        for (int j = 0; j < 8; j++) {
            int m = tx * 8 + j;
            ok = ok && ((m == n) || (pn > acc[i][j]));
        }
        flg[n][tx] = ok ? 1 : 0;
        size_t base = ((size_t)l * NN + n) * NN + tx * 8;
        *(float4*)&g_tmp[base] = make_float4(acc[i][0] * INV_T, acc[i][1] * INV_T,
                                             acc[i][2] * INV_T, acc[i][3] * INV_T);
        *(float4*)&g_tmp[base + 4] = make_float4(acc[i][4] * INV_T, acc[i][5] * INV_T,
                                                 acc[i][6] * INV_T, acc[i][7] * INV_T);
    }
    __syncthreads();
    if (tid < 128) {
        bool ok = true;
#pragma unroll
        for (int x = 0; x < 16; x++) ok = ok && (flg[tid][x] != 0);
        unsigned m = __ballot_sync(0xffffffffu, ok);
        if ((tid & 31) == 0) atomicAdd(&g_cnt[stepIdx], (unsigned)__popc(m));
    }
}

// g_tmp[l][n][m] -> out[n][m][kbase + l] (coalesced both sides via 32x32 smem tile)
__global__ void transpose_kernel(float* __restrict__ out, int Lp, int kbase) {
    __shared__ float tile[32][33];
    int n = blockIdx.z;
    int l0 = blockIdx.x * 32, m0 = blockIdx.y * 32;
    int tx = threadIdx.x, ty = threadIdx.y;
#pragma unroll
    for (int i = 0; i < 4; i++) {
        int l = l0 + ty + i * 8;
        if (l < Lp) tile[ty + i * 8][tx] = g_tmp[((size_t)l * NN + n) * NN + m0 + tx];
    }
    __syncthreads();
#pragma unroll
    for (int i = 0; i < 4; i++) {
        int m = m0 + ty + i * 8;
        int l = l0 + tx;
        if (l < Lp) out[((size_t)n * NN + m) * KTOT + kbase + l] = tile[tx][ty + i * 8];
    }
}

__global__ void ytrue_kernel(float* __restrict__ out) {
    int idx = blockIdx.x * 256 + threadIdx.x;
    if (idx < NN * KTOT) out[(size_t)NN * NN * KTOT + idx] = (float)(idx / KTOT);
}

__global__ void acc_kernel(float* __restrict__ out) {
    size_t off = (size_t)NN * NN * KTOT + (size_t)NN * KTOT;
    out[off + 0] = (float)g_cnt[0] / (float)(NN * L1S);
    out[off + 1] = (float)g_cnt[1] / (float)(NN * L2S);
}

extern "C" void kernel_launch(void* const* d_in, const int* in_sizes, int n_in,
                              void* d_out, int out_size) {
    const float* ts  = (const float*)d_in[0];
    const float* pts = (const float*)d_in[1];
    const float* W1  = (const float*)d_in[2];
    const float* b1  = (const float*)d_in[3];
    const float* W2  = (const float*)d_in[4];
    const float* b2  = (const float*)d_in[5];
    float* out = (float*)d_out;

    init_kernel<<<1, 1>>>();
    const float* Ws[2] = {W1, W2};
    const float* bs[2] = {b1, b2};
    int kb = 0;
    for (int si = 0; si < 2; si++) {
        int step = si + 1;
        int Lp = LFULL - step;
        tb_kernel<<<Lp, 128>>>(ts, bs[si], Lp, step);
        gemmU_kernel<<<dim3(4, Lp), 256>>>(ts, Ws[si], Lp, step);
        gemmL_kernel<<<Lp, 256>>>(pts, Lp, si);
        transpose_kernel<<<dim3(32, 4, 128), dim3(32, 8)>>>(out, Lp, kb);
        kb += Lp;
    }
    ytrue_kernel<<<(NN * KTOT + 255) / 256, 256>>>(out);
    acc_kernel<<<1, 1>>>(out);
}

// round 7
// speedup vs baseline: 2.0362x; 2.0362x over previous
#include <cuda_runtime.h>
#include <cstdint>

#define NN 128
#define LFULL 1024
#define CC 512
#define KTOT 2045
#define L1S 1023
#define L2S 1022

static __device__ __constant__ float INV_T = 14.2857142857142857f; // 1/0.07

// ---------------- device scratch (allocation-free rule) ----------------
__device__ float g_U[(size_t)NN * L1S * CC];     // 268 MB: U = T@W (tf32-rounded), [(n*Lp+l)][p]
__device__ float g_Wt[CC * CC];                  // W transposed + tf32-rounded: Wt[p][c]
__device__ float g_tb[L1S * NN];                 // tb[l][n]
__device__ float g_tmp[(size_t)L1S * NN * NN];   // 67 MB: [l][n][m] (already /T)
__device__ unsigned int g_cnt[2];

// ---------------- helpers ----------------
__device__ __forceinline__ float tf32r(float x) {
    unsigned r;
    asm("cvt.rna.tf32.f32 %0, %1;" : "=r"(r) : "f"(x));
    return __uint_as_float(r);
}
__device__ __forceinline__ void cp16(unsigned s, const void* g) {
    asm volatile("cp.async.cg.shared.global [%0], [%1], 16;" :: "r"(s), "l"(g));
}
#define CP_COMMIT() asm volatile("cp.async.commit_group;" ::: "memory")
#define CP_WAIT(n)  asm volatile("cp.async.wait_group %0;" :: "n"(n) : "memory")

// D += A*B : m16n8k8 tf32 (A row-major, B col-major), fp32 accum
__device__ __forceinline__ void mma1688(float* c, const unsigned* a, const unsigned* b) {
    asm volatile(
        "mma.sync.aligned.m16n8k8.row.col.f32.tf32.tf32.f32 "
        "{%0,%1,%2,%3}, {%4,%5,%6,%7}, {%8,%9}, {%0,%1,%2,%3};"
        : "+f"(c[0]), "+f"(c[1]), "+f"(c[2]), "+f"(c[3])
        : "r"(a[0]), "r"(a[1]), "r"(a[2]), "r"(a[3]), "r"(b[0]), "r"(b[1]));
}

// smem tile geometry: 128 rows x 32 k, pitch 36 floats (conflict-free frag loads)
#define KS 32
#define PITCH 36
#define TILE_B (128 * PITCH * 4)      // 18432 bytes
// buffer offsets: A0, B0, A1, B1
#define OFF_A(buf) ((buf) ? 2 * TILE_B : 0)
#define OFF_B(buf) (OFF_A(buf) + TILE_B)
#define SM_GEMM (4 * TILE_B)          // 73728
#define U_SM_SIZE (SM_GEMM + 512)     // + rows[]
#define L_SM_SIZE SM_GEMM
#define SPAD 132

// ======================= misc kernels (proven in R1) =======================
__global__ void init_kernel() { g_cnt[0] = 0u; g_cnt[1] = 0u; }

__global__ void tb_kernel(const float* __restrict__ t, const float* __restrict__ b,
                          int Lp, int step) {
    int l = blockIdx.x, n = threadIdx.x;
    const float4* r4 = (const float4*)(t + ((size_t)n * LFULL + l + step) * CC);
    const float4* b4 = (const float4*)b;
    float s = 0.f;
#pragma unroll 8
    for (int i = 0; i < CC / 4; i++) {
        float4 a = r4[i], bb = b4[i];
        s += a.x * bb.x + a.y * bb.y + a.z * bb.z + a.w * bb.w;
    }
    g_tb[l * NN + n] = s;
}

// g_Wt[p][c] = tf32_round(W[c][p])
__global__ void wt_kernel(const float* __restrict__ W) {
    __shared__ float t[32][33];
    int c0 = blockIdx.y * 32, p0 = blockIdx.x * 32;
    int tx = threadIdx.x, ty = threadIdx.y;
#pragma unroll
    for (int i = 0; i < 4; i++)
        t[ty + 8 * i][tx] = W[(size_t)(c0 + ty + 8 * i) * CC + p0 + tx];
    __syncthreads();
#pragma unroll
    for (int i = 0; i < 4; i++)
        g_Wt[(size_t)(p0 + ty + 8 * i) * CC + c0 + tx] = tf32r(t[tx][ty + 8 * i]);
}

__global__ void transpose_kernel(float* __restrict__ out, int Lp, int kbase) {
    __shared__ float tile[32][33];
    int n = blockIdx.z;
    int l0 = blockIdx.x * 32, m0 = blockIdx.y * 32;
    int tx = threadIdx.x, ty = threadIdx.y;
#pragma unroll
    for (int i = 0; i < 4; i++) {
        int l = l0 + ty + i * 8;
        if (l < Lp) tile[ty + i * 8][tx] = g_tmp[((size_t)l * NN + n) * NN + m0 + tx];
    }
    __syncthreads();
#pragma unroll
    for (int i = 0; i < 4; i++) {
        int m = m0 + ty + i * 8;
        int l = l0 + tx;
        if (l < Lp) out[((size_t)n * NN + m) * KTOT + kbase + l] = tile[tx][ty + i * 8];
    }
}

__global__ void ytrue_kernel(float* __restrict__ out) {
    int idx = blockIdx.x * 256 + threadIdx.x;
    if (idx < NN * KTOT) out[(size_t)NN * NN * KTOT + idx] = (float)(idx / KTOT);
}

__global__ void acc_kernel(float* __restrict__ out) {
    size_t off = (size_t)NN * NN * KTOT + (size_t)NN * KTOT;
    out[off + 0] = (float)g_cnt[0] / (float)(NN * L1S);
    out[off + 1] = (float)g_cnt[1] / (float)(NN * L2S);
}

// ============ shared warp microkernel: 8 warps, warp tile 32x64 ============
// acc[mi(2)][ni(8)][4]; warp grid: wr = wid&3 (M), wc = wid>>2 (N)
__device__ __forceinline__ void compute_stage(const char* sm, int buf,
                                              int wr, int wc, int gid, int tig,
                                              float acc[2][8][4]) {
    const unsigned* Asm = (const unsigned*)(sm + OFF_A(buf));
    const unsigned* Bsm = (const unsigned*)(sm + OFF_B(buf));
#pragma unroll
    for (int k8 = 0; k8 < KS / 8; k8++) {
        int k0 = k8 * 8;
        unsigned af[2][4];
#pragma unroll
        for (int mi = 0; mi < 2; mi++) {
            const unsigned* p = Asm + (wr * 32 + mi * 16 + gid) * PITCH + k0 + tig;
            af[mi][0] = p[0];
            af[mi][1] = p[8 * PITCH];
            af[mi][2] = p[4];
            af[mi][3] = p[8 * PITCH + 4];
        }
        unsigned bf[8][2];
#pragma unroll
        for (int ni = 0; ni < 8; ni++) {
            const unsigned* q = Bsm + (wc * 64 + ni * 8 + gid) * PITCH + k0 + tig;
            bf[ni][0] = q[0];
            bf[ni][1] = q[4];
        }
#pragma unroll
        for (int mi = 0; mi < 2; mi++)
#pragma unroll
            for (int ni = 0; ni < 8; ni++)
                mma1688(acc[mi][ni], af[mi], bf[ni]);
    }
}

// ======================= gemmU: U = T @ Wt^T =======================
// grid (4, Lp): blockIdx.x = 128-col chunk of 512, blockIdx.y = 128-row tile
__device__ __forceinline__ void u_load(const float* __restrict__ T,
                                       const unsigned* __restrict__ rows,
                                       char* sm, unsigned sb, int buf, int kt,
                                       int colbase, int tid) {
    unsigned ab = sb + OFF_A(buf);
    char* bbp = sm + OFF_B(buf);
    unsigned bb = sb + OFF_B(buf);
    (void)bbp;
#pragma unroll
    for (int j = 0; j < 4; j++) {                 // B: Wt rows colbase..+127 (cp.async)
        int idx = tid + j * 256;
        int row = idx >> 3, c4 = idx & 7;
        cp16(bb + row * (PITCH * 4) + c4 * 16,
             g_Wt + (size_t)(colbase + row) * CC + kt + c4 * 4);
    }
    char* abp = sm + OFF_A(buf);
#pragma unroll
    for (int j = 0; j < 4; j++) {                 // A: T rows (LDG + cvt + STS)
        int idx = tid + j * 256;
        int row = idx >> 3, c4 = idx & 7;
        float4 v = *(const float4*)(T + rows[row] + kt + c4 * 4);
        v.x = tf32r(v.x); v.y = tf32r(v.y); v.z = tf32r(v.z); v.w = tf32r(v.w);
        *(float4*)(abp + row * (PITCH * 4) + c4 * 16) = v;
    }
    (void)ab;
    CP_COMMIT();
}

__global__ void __launch_bounds__(256, 2)
gemmU_mma(const float* __restrict__ T, int Lp, int step) {
    extern __shared__ char sm[];
    unsigned sb = (unsigned)__cvta_generic_to_shared(sm);
    int tid = threadIdx.x, wid = tid >> 5, lid = tid & 31;
    int wr = wid & 3, wc = wid >> 2, gid = lid >> 2, tig = lid & 3;
    int colbase = blockIdx.x * 128;
    int r0 = blockIdx.y * 128;

    unsigned* rows = (unsigned*)(sm + SM_GEMM);
    if (tid < 128) {
        int r = r0 + tid;
        int n = r / Lp, l = r - n * Lp;
        rows[tid] = (unsigned)((n * LFULL + l + step) * CC);
    }
    __syncthreads();

    float acc[2][8][4] = {};
    u_load(T, rows, sm, sb, 0, 0, colbase, tid);
    for (int s = 0; s < 16; s++) {
        if (s + 1 < 16) {
            u_load(T, rows, sm, sb, (s + 1) & 1, (s + 1) * KS, colbase, tid);
            CP_WAIT(1);
        } else {
            CP_WAIT(0);
        }
        __syncthreads();
        compute_stage(sm, s & 1, wr, wc, gid, tig, acc);
        __syncthreads();
    }

    // epilogue: store tf32-rounded U (float2 per c-pair, sector-complete)
#pragma unroll
    for (int mi = 0; mi < 2; mi++) {
        int rA = r0 + wr * 32 + mi * 16 + gid;
#pragma unroll
        for (int ni = 0; ni < 8; ni++) {
            int col = colbase + wc * 64 + ni * 8 + 2 * tig;
            float2 v0 = make_float2(tf32r(acc[mi][ni][0]), tf32r(acc[mi][ni][1]));
            float2 v1 = make_float2(tf32r(acc[mi][ni][2]), tf32r(acc[mi][ni][3]));
            *(float2*)(g_U + (size_t)rA * CC + col) = v0;
            *(float2*)(g_U + (size_t)(rA + 8) * CC + col) = v1;
        }
    }
}

// ======================= gemmL: per-l 128x128x512 Gram =======================
__device__ __forceinline__ void l_load(const float* __restrict__ P,
                                       char* sm, unsigned sb, int buf, int kt,
                                       int l, int Lp, int tid) {
    unsigned ab = sb + OFF_A(buf);
#pragma unroll
    for (int j = 0; j < 4; j++) {                 // A: U rows n (cp.async, pre-rounded)
        int idx = tid + j * 256;
        int row = idx >> 3, c4 = idx & 7;
        cp16(ab + row * (PITCH * 4) + c4 * 16,
             g_U + ((size_t)row * Lp + l) * CC + kt + c4 * 4);
    }
    char* bbp = sm + OFF_B(buf);
#pragma unroll
    for (int j = 0; j < 4; j++) {                 // B: P rows m (LDG + cvt + STS)
        int idx = tid + j * 256;
        int row = idx >> 3, c4 = idx & 7;
        float4 v = *(const float4*)(P + ((size_t)row * LFULL + l) * CC + kt + c4 * 4);
        v.x = tf32r(v.x); v.y = tf32r(v.y); v.z = tf32r(v.z); v.w = tf32r(v.w);
        *(float4*)(bbp + row * (PITCH * 4) + c4 * 16) = v;
    }
    CP_COMMIT();
}

__global__ void __launch_bounds__(256, 2)
gemmL_mma(const float* __restrict__ P, int Lp, int stepIdx) {
    extern __shared__ char sm[];
    unsigned sb = (unsigned)__cvta_generic_to_shared(sm);
    int tid = threadIdx.x, wid = tid >> 5, lid = tid & 31;
    int wr = wid & 3, wc = wid >> 2, gid = lid >> 2, tig = lid & 3;
    int l = blockIdx.x;

    float acc[2][8][4] = {};
    l_load(P, sm, sb, 0, 0, l, Lp, tid);
    for (int s = 0; s < 16; s++) {
        if (s + 1 < 16) {
            l_load(P, sm, sb, (s + 1) & 1, (s + 1) * KS, l, Lp, tid);
            CP_WAIT(1);
        } else {
            CP_WAIT(0);
        }
        __syncthreads();
        compute_stage(sm, s & 1, wr, wc, gid, tig, acc);
        __syncthreads();
    }

    // epilogue: S[n][m] = (acc + tb[n]) * INV_T  (smem reuses the k-buffers)
    float* S = (float*)sm;
#pragma unroll
    for (int mi = 0; mi < 2; mi++) {
        int n0 = wr * 32 + mi * 16 + gid;
        float tbl = g_tb[l * NN + n0];
        float tbh = g_tb[l * NN + n0 + 8];
#pragma unroll
        for (int ni = 0; ni < 8; ni++) {
            int col = wc * 64 + ni * 8 + 2 * tig;
            S[n0 * SPAD + col]           = (acc[mi][ni][0] + tbl) * INV_T;
            S[n0 * SPAD + col + 1]       = (acc[mi][ni][1] + tbl) * INV_T;
            S[(n0 + 8) * SPAD + col]     = (acc[mi][ni][2] + tbh) * INV_T;
            S[(n0 + 8) * SPAD + col + 1] = (acc[mi][ni][3] + tbh) * INV_T;
        }
    }
    __syncthreads();

    // NCE accuracy (scaling by INV_T>0 preserves order)
    if (tid < 128) {
        float pos = S[tid * SPAD + tid];
        bool ok = true;
#pragma unroll 8
        for (int m = 0; m < NN; m++)
            ok = ok && ((m == tid) || (pos > S[tid * SPAD + m]));
        unsigned msk = __ballot_sync(0xffffffffu, ok);
        if (lid == 0) atomicAdd(&g_cnt[stepIdx], (unsigned)__popc(msk));
    }
    // coalesced staged store: S[n][m] -> g_tmp[l][n][m]
    for (int idx = tid; idx < NN * NN / 4; idx += 256) {
        int n2 = idx >> 5, m4 = (idx & 31) * 4;
        float4 v = *(float4*)&S[n2 * SPAD + m4];
        *(float4*)&g_tmp[((size_t)l * NN + n2) * NN + m4] = v;
    }
}

// ======================= launch =======================
extern "C" void kernel_launch(void* const* d_in, const int* in_sizes, int n_in,
                              void* d_out, int out_size) {
    const float* ts  = (const float*)d_in[0];
    const float* pts = (const float*)d_in[1];
    const float* W1  = (const float*)d_in[2];
    const float* b1  = (const float*)d_in[3];
    const float* W2  = (const float*)d_in[4];
    const float* b2  = (const float*)d_in[5];
    float* out = (float*)d_out;

    static bool attr_done = false;
    if (!attr_done) {
        cudaFuncSetAttribute(gemmU_mma, cudaFuncAttributeMaxDynamicSharedMemorySize, U_SM_SIZE);
        cudaFuncSetAttribute(gemmL_mma, cudaFuncAttributeMaxDynamicSharedMemorySize, L_SM_SIZE);
        attr_done = true;
    }

    init_kernel<<<1, 1>>>();
    const float* Ws[2] = {W1, W2};
    const float* bs[2] = {b1, b2};
    int kb = 0;
    for (int si = 0; si < 2; si++) {
        int step = si + 1;
        int Lp = LFULL - step;
        wt_kernel<<<dim3(16, 16), dim3(32, 8)>>>(Ws[si]);
        tb_kernel<<<Lp, 128>>>(ts, bs[si], Lp, step);
        gemmU_mma<<<dim3(4, Lp), 256, U_SM_SIZE>>>(ts, Lp, step);
        gemmL_mma<<<Lp, 256, L_SM_SIZE>>>(pts, Lp, si);
        transpose_kernel<<<dim3(32, 4, 128), dim3(32, 8)>>>(out, Lp, kb);
        kb += Lp;
    }
    ytrue_kernel<<<(NN * KTOT + 255) / 256, 256>>>(out);
    acc_kernel<<<1, 1>>>(out);
}

// round 11
// speedup vs baseline: 2.3197x; 1.1392x over previous
#include <cuda_runtime.h>
#include <cstdint>

#define NN 128
#define LFULL 1024
#define CC 512
#define KTOT 2045
#define L1S 1023
#define L2S 1022

static __device__ __constant__ float INV_T = 14.2857142857142857f; // 1/0.07

// ---------------- device scratch (allocation-free rule) ----------------
// g_U and g_Wt are stored K-PERMUTED within each 8-float group:
//   position 2t   holds original k = t
//   position 2t+1 holds original k = t+4      (t = 0..3)
__device__ float g_U[(size_t)NN * L1S * CC];     // 268 MB, tf32-rounded + permuted
__device__ float g_Wt[CC * CC];                  // W^T, tf32-rounded + permuted
__device__ float g_tb[L1S * NN];                 // tb[l][n]
__device__ float g_tmp[(size_t)L1S * NN * NN];   // 67 MB: [l][n][m] (already /T)
__device__ unsigned int g_cnt[2];

// ---------------- helpers ----------------
__device__ __forceinline__ float tf32r(float x) {
    unsigned r;
    asm("cvt.rna.tf32.f32 %0, %1;" : "=r"(r) : "f"(x));
    return __uint_as_float(r);
}
__device__ __forceinline__ void cp16(unsigned s, const void* g) {
    asm volatile("cp.async.cg.shared.global [%0], [%1], 16;" :: "r"(s), "l"(g));
}
#define CP_COMMIT() asm volatile("cp.async.commit_group;" ::: "memory")
#define CP_WAIT(n)  asm volatile("cp.async.wait_group %0;" :: "n"(n) : "memory")

// D += A*B : m16n8k8 tf32 (A row-major, B col-major), fp32 accum
__device__ __forceinline__ void mma1688(float* c, const unsigned* a, const unsigned* b) {
    asm volatile(
        "mma.sync.aligned.m16n8k8.row.col.f32.tf32.tf32.f32 "
        "{%0,%1,%2,%3}, {%4,%5,%6,%7}, {%8,%9}, {%0,%1,%2,%3};"
        : "+f"(c[0]), "+f"(c[1]), "+f"(c[2]), "+f"(c[3])
        : "r"(a[0]), "r"(a[1]), "r"(a[2]), "r"(a[3]), "r"(b[0]), "r"(b[1]));
}

// smem tile: 128 rows x 32 k (permuted), pitch 36 floats (144B)
#define KS 32
#define PITCHF 36
#define ROWB (PITCHF * 4)
#define TILE_B (128 * ROWB)            // 18432 bytes
#define OFF_A(buf) ((buf) * 2 * TILE_B)
#define OFF_B(buf) (OFF_A(buf) + TILE_B)
#define SM_GEMM (6 * TILE_B)           // 110592 (3-stage ring)
#define SM_TOTAL (SM_GEMM + 512)
#define SPAD 132

// ======================= misc kernels =======================
__global__ void init_kernel() { g_cnt[0] = 0u; g_cnt[1] = 0u; }

__global__ void tb_kernel(const float* __restrict__ t, const float* __restrict__ b,
                          int Lp, int step) {
    int l = blockIdx.x, n = threadIdx.x;
    const float4* r4 = (const float4*)(t + ((size_t)n * LFULL + l + step) * CC);
    const float4* b4 = (const float4*)b;
    float s = 0.f;
#pragma unroll 8
    for (int i = 0; i < CC / 4; i++) {
        float4 a = r4[i], bb = b4[i];
        s += a.x * bb.x + a.y * bb.y + a.z * bb.z + a.w * bb.w;
    }
    g_tb[l * NN + n] = s;
}

// g_Wt[p][perm(c)] = tf32_round(W[c][p]);  perm within 8-groups
__global__ void wt_kernel(const float* __restrict__ W) {
    __shared__ float t[32][33];
    int c0 = blockIdx.y * 32, p0 = blockIdx.x * 32;
    int tx = threadIdx.x, ty = threadIdx.y;
#pragma unroll
    for (int i = 0; i < 4; i++)
        t[ty + 8 * i][tx] = W[(size_t)(c0 + ty + 8 * i) * CC + p0 + tx];
    __syncthreads();
    int cp_ = (tx & ~7) | (((tx & 3) << 1) | ((tx >> 2) & 1));
#pragma unroll
    for (int i = 0; i < 4; i++)
        g_Wt[(size_t)(p0 + ty + 8 * i) * CC + c0 + cp_] = tf32r(t[tx][ty + 8 * i]);
}

__global__ void transpose_kernel(float* __restrict__ out, int Lp, int kbase) {
    __shared__ float tile[32][33];
    int n = blockIdx.z;
    int l0 = blockIdx.x * 32, m0 = blockIdx.y * 32;
    int tx = threadIdx.x, ty = threadIdx.y;
#pragma unroll
    for (int i = 0; i < 4; i++) {
        int l = l0 + ty + i * 8;
        if (l < Lp) tile[ty + i * 8][tx] = g_tmp[((size_t)l * NN + n) * NN + m0 + tx];
    }
    __syncthreads();
#pragma unroll
    for (int i = 0; i < 4; i++) {
        int m = m0 + ty + i * 8;
        int l = l0 + tx;
        if (l < Lp) out[((size_t)n * NN + m) * KTOT + kbase + l] = tile[tx][ty + i * 8];
    }
}

__global__ void ytrue_kernel(float* __restrict__ out) {
    int idx = blockIdx.x * 256 + threadIdx.x;
    if (idx < NN * KTOT) out[(size_t)NN * NN * KTOT + idx] = (float)(idx / KTOT);
}

__global__ void acc_kernel(float* __restrict__ out) {
    size_t off = (size_t)NN * NN * KTOT + (size_t)NN * KTOT;
    out[off + 0] = (float)g_cnt[0] / (float)(NN * L1S);
    out[off + 1] = (float)g_cnt[1] / (float)(NN * L2S);
}

// ============ warp microkernel: 8 warps, warp tile 32x64, LDS.64 frags ============
__device__ __forceinline__ void compute_half(const char* sm, int buf, int h,
                                             int wr, int wc, int gid, int tig,
                                             float acc[2][8][4]) {
    const char* Ab = sm + OFF_A(buf);
    const char* Bb = sm + OFF_B(buf);
#pragma unroll
    for (int k8 = h * 2; k8 < h * 2 + 2; k8++) {
        uint2 afl[2], afh[2];
#pragma unroll
        for (int mi = 0; mi < 2; mi++) {
            int r = wr * 32 + mi * 16 + gid;
            afl[mi] = *(const uint2*)(Ab + r * ROWB + k8 * 32 + tig * 8);
            afh[mi] = *(const uint2*)(Ab + (r + 8) * ROWB + k8 * 32 + tig * 8);
        }
        uint2 bf2[8];
#pragma unroll
        for (int ni = 0; ni < 8; ni++) {
            int c = wc * 64 + ni * 8 + gid;
            bf2[ni] = *(const uint2*)(Bb + c * ROWB + k8 * 32 + tig * 8);
        }
#pragma unroll
        for (int mi = 0; mi < 2; mi++) {
            unsigned a[4] = {afl[mi].x, afh[mi].x, afl[mi].y, afh[mi].y};
#pragma unroll
            for (int ni = 0; ni < 8; ni++) {
                unsigned b[2] = {bf2[ni].x, bf2[ni].y};
                mma1688(acc[mi][ni], a, b);
            }
        }
    }
}

// permute 8 consecutive k (two float4) into paired layout, with tf32 rounding
__device__ __forceinline__ void sts_perm(char* dst, float4 a, float4 b, bool rnd) {
    float4 v0, v1;
    if (rnd) {
        v0 = make_float4(tf32r(a.x), tf32r(b.x), tf32r(a.y), tf32r(b.y));
        v1 = make_float4(tf32r(a.z), tf32r(b.z), tf32r(a.w), tf32r(b.w));
    } else {
        v0 = make_float4(a.x, b.x, a.y, b.y);
        v1 = make_float4(a.z, b.z, a.w, b.w);
    }
    *(float4*)dst = v0;
    *(float4*)(dst + 16) = v1;
}

// ======================= gemmU: U = T @ Wt^T =======================
// grid (4, Lp); A = T (LDG+cvt+perm+STS), B = g_Wt (cp.async, pre-permuted)
__global__ void __launch_bounds__(256, 2)
gemmU_mma(const float* __restrict__ T, int Lp, int step) {
    extern __shared__ char sm[];
    unsigned sb = (unsigned)__cvta_generic_to_shared(sm);
    int tid = threadIdx.x, wid = tid >> 5, lid = tid & 31;
    int wr = wid & 3, wc = wid >> 2, gid = lid >> 2, tig = lid & 3;
    int colbase = blockIdx.x * 128;
    int r0 = blockIdx.y * 128;

    unsigned* rows = (unsigned*)(sm + SM_GEMM);
    if (tid < 128) {
        int r = r0 + tid;
        int n = r / Lp, l = r - n * Lp;
        rows[tid] = (unsigned)((n * LFULL + l + step) * CC);
    }
    __syncthreads();

    int arow = tid >> 2, ag8 = tid & 3;       // A chunk ids (iter adds 64 rows)
    int brow = tid >> 3, bc4 = tid & 7;       // B cp chunk ids (iter adds 32 rows)

    // prologue: stages 0,1
#pragma unroll
    for (int ps = 0; ps < 2; ps++) {
        int kt = ps * KS;
        unsigned bb = sb + OFF_B(ps);
#pragma unroll
        for (int j = 0; j < 4; j++) {
            int row = brow + j * 32;
            cp16(bb + row * ROWB + bc4 * 16,
                 g_Wt + (size_t)(colbase + row) * CC + kt + bc4 * 4);
        }
        char* ab = sm + OFF_A(ps);
#pragma unroll
        for (int it = 0; it < 2; it++) {
            int row = arow + it * 64;
            const float* src = T + rows[row] + kt + ag8 * 8;
            float4 a = *(const float4*)src, b = *(const float4*)(src + 4);
            sts_perm(ab + row * ROWB + ag8 * 32, a, b, true);
        }
        CP_COMMIT();
    }

    float acc[2][8][4] = {};
#pragma unroll 1
    for (int s = 0; s < 16; s++) {
        if (s < 15) CP_WAIT(1); else CP_WAIT(0);
        __syncthreads();
        int buf = s % 3;
        bool pf = (s + 2 < 16);
        float4 a0, b0, a1, b1;
        if (pf) {
            int kt = (s + 2) * KS, nb = (s + 2) % 3;
            unsigned bb = sb + OFF_B(nb);
#pragma unroll
            for (int j = 0; j < 4; j++) {
                int row = brow + j * 32;
                cp16(bb + row * ROWB + bc4 * 16,
                     g_Wt + (size_t)(colbase + row) * CC + kt + bc4 * 4);
            }
            const float* s0 = T + rows[arow] + kt + ag8 * 8;
            const float* s1 = T + rows[arow + 64] + kt + ag8 * 8;
            a0 = *(const float4*)s0; b0 = *(const float4*)(s0 + 4);
            a1 = *(const float4*)s1; b1 = *(const float4*)(s1 + 4);
        }
        compute_half(sm, buf, 0, wr, wc, gid, tig, acc);
        if (pf) {
            char* ab = sm + OFF_A((s + 2) % 3);
            sts_perm(ab + arow * ROWB + ag8 * 32, a0, b0, true);
            sts_perm(ab + (arow + 64) * ROWB + ag8 * 32, a1, b1, true);
        }
        compute_half(sm, buf, 1, wr, wc, gid, tig, acc);
        if (pf) CP_COMMIT();
    }

    // epilogue: store tf32-rounded U in PERMUTED column layout
    int p0 = ((2 * tig) & 3) * 2 + ((tig >> 1) & 1);   // perm(2*tig)
    int p1 = p0 + 2;                                    // perm(2*tig+1)
#pragma unroll
    for (int mi = 0; mi < 2; mi++) {
        int rA = r0 + wr * 32 + mi * 16 + gid;
#pragma unroll
        for (int ni = 0; ni < 8; ni++) {
            int base8 = colbase + wc * 64 + ni * 8;
            float* u0 = g_U + (size_t)rA * CC + base8;
            float* u1 = g_U + (size_t)(rA + 8) * CC + base8;
            u0[p0] = tf32r(acc[mi][ni][0]);
            u0[p1] = tf32r(acc[mi][ni][1]);
            u1[p0] = tf32r(acc[mi][ni][2]);
            u1[p1] = tf32r(acc[mi][ni][3]);
        }
    }
}

// ======================= gemmL: per-l 128x128x512 Gram =======================
// A = g_U (cp.async, pre-permuted+rounded), B = P (LDG+cvt+perm+STS)
__global__ void __launch_bounds__(256, 2)
gemmL_mma(const float* __restrict__ P, int Lp, int stepIdx) {
    extern __shared__ char sm[];
    unsigned sb = (unsigned)__cvta_generic_to_shared(sm);
    int tid = threadIdx.x, wid = tid >> 5, lid = tid & 31;
    int wr = wid & 3, wc = wid >> 2, gid = lid >> 2, tig = lid & 3;
    int l = blockIdx.x;

    int arow = tid >> 3, ac4 = tid & 7;       // A cp chunks
    int brow = tid >> 2, bg8 = tid & 3;       // B LDG chunks

    // prologue: stages 0,1
#pragma unroll
    for (int ps = 0; ps < 2; ps++) {
        int kt = ps * KS;
        unsigned ab = sb + OFF_A(ps);
#pragma unroll
        for (int j = 0; j < 4; j++) {
            int row = arow + j * 32;
            cp16(ab + row * ROWB + ac4 * 16,
                 g_U + ((size_t)row * Lp + l) * CC + kt + ac4 * 4);
        }
        char* bbp = sm + OFF_B(ps);
#pragma unroll
        for (int it = 0; it < 2; it++) {
            int row = brow + it * 64;
            const float* src = P + ((size_t)row * LFULL + l) * CC + kt + bg8 * 8;
            float4 a = *(const float4*)src, b = *(const float4*)(src + 4);
            sts_perm(bbp + row * ROWB + bg8 * 32, a, b, true);
        }
        CP_COMMIT();
    }

    float acc[2][8][4] = {};
#pragma unroll 1
    for (int s = 0; s < 16; s++) {
        if (s < 15) CP_WAIT(1); else CP_WAIT(0);
        __syncthreads();
        int buf = s % 3;
        bool pf = (s + 2 < 16);
        float4 a0, b0, a1, b1;
        if (pf) {
            int kt = (s + 2) * KS, nb = (s + 2) % 3;
            unsigned ab = sb + OFF_A(nb);
#pragma unroll
            for (int j = 0; j < 4; j++) {
                int row = arow + j * 32;
                cp16(ab + row * ROWB + ac4 * 16,
                     g_U + ((size_t)row * Lp + l) * CC + kt + ac4 * 4);
            }
            const float* s0 = P + ((size_t)brow * LFULL + l) * CC + kt + bg8 * 8;
            const float* s1 = P + ((size_t)(brow + 64) * LFULL + l) * CC + kt + bg8 * 8;
            a0 = *(const float4*)s0; b0 = *(const float4*)(s0 + 4);
            a1 = *(const float4*)s1; b1 = *(const float4*)(s1 + 4);
        }
        compute_half(sm, buf, 0, wr, wc, gid, tig, acc);
        if (pf) {
            char* bbp = sm + OFF_B((s + 2) % 3);
            sts_perm(bbp + brow * ROWB + bg8 * 32, a0, b0, true);
            sts_perm(bbp + (brow + 64) * ROWB + bg8 * 32, a1, b1, true);
        }
        compute_half(sm, buf, 1, wr, wc, gid, tig, acc);
        if (pf) CP_COMMIT();
    }
    __syncthreads();   // protect smem before epilogue S overwrites buffers

    // epilogue: S[n][m] = (acc + tb[n]) * INV_T
    float* S = (float*)sm;
#pragma unroll
    for (int mi = 0; mi < 2; mi++) {
        int n0 = wr * 32 + mi * 16 + gid;
        float tbl = g_tb[l * NN + n0];
        float tbh = g_tb[l * NN + n0 + 8];
#pragma unroll
        for (int ni = 0; ni < 8; ni++) {
            int col = wc * 64 + ni * 8 + 2 * tig;
            S[n0 * SPAD + col]           = (acc[mi][ni][0] + tbl) * INV_T;
            S[n0 * SPAD + col + 1]       = (acc[mi][ni][1] + tbl) * INV_T;
            S[(n0 + 8) * SPAD + col]     = (acc[mi][ni][2] + tbh) * INV_T;
            S[(n0 + 8) * SPAD + col + 1] = (acc[mi][ni][3] + tbh) * INV_T;
        }
    }
    __syncthreads();

    // NCE accuracy (INV_T > 0 preserves ordering)
    if (tid < 128) {
        float pos = S[tid * SPAD + tid];
        bool ok = true;
#pragma unroll 8
        for (int m = 0; m < NN; m++)
            ok = ok && ((m == tid) || (pos > S[tid * SPAD + m]));
        unsigned msk = __ballot_sync(0xffffffffu, ok);
        if (lid == 0) atomicAdd(&g_cnt[stepIdx], (unsigned)__popc(msk));
    }
    // coalesced staged store: S[n][m] -> g_tmp[l][n][m]
    for (int idx = tid; idx < NN * NN / 4; idx += 256) {
        int n2 = idx >> 5, m4 = (idx & 31) * 4;
        float4 v = *(float4*)&S[n2 * SPAD + m4];
        *(float4*)&g_tmp[((size_t)l * NN + n2) * NN + m4] = v;
    }
}

// ======================= launch =======================
extern "C" void kernel_launch(void* const* d_in, const int* in_sizes, int n_in,
                              void* d_out, int out_size) {
    const float* ts  = (const float*)d_in[0];
    const float* pts = (const float*)d_in[1];
    const float* W1  = (const float*)d_in[2];
    const float* b1  = (const float*)d_in[3];
    const float* W2  = (const float*)d_in[4];
    const float* b2  = (const float*)d_in[5];
    float* out = (float*)d_out;

    static bool attr_done = false;
    if (!attr_done) {
        cudaFuncSetAttribute(gemmU_mma, cudaFuncAttributeMaxDynamicSharedMemorySize, SM_TOTAL);
        cudaFuncSetAttribute(gemmL_mma, cudaFuncAttributeMaxDynamicSharedMemorySize, SM_TOTAL);
        attr_done = true;
    }

    init_kernel<<<1, 1>>>();
    const float* Ws[2] = {W1, W2};
    const float* bs[2] = {b1, b2};
    int kb = 0;
    for (int si = 0; si < 2; si++) {
        int step = si + 1;
        int Lp = LFULL - step;
        wt_kernel<<<dim3(16, 16), dim3(32, 8)>>>(Ws[si]);
        tb_kernel<<<Lp, 128>>>(ts, bs[si], Lp, step);
        gemmU_mma<<<dim3(4, Lp), 256, SM_TOTAL>>>(ts, Lp, step);
        gemmL_mma<<<Lp, 256, SM_TOTAL>>>(pts, Lp, si);
        transpose_kernel<<<dim3(32, 4, 128), dim3(32, 8)>>>(out, Lp, kb);
        kb += Lp;
    }
    ytrue_kernel<<<(NN * KTOT + 255) / 256, 256>>>(out);
    acc_kernel<<<1, 1>>>(out);
}